// round 15
// baseline (speedup 1.0000x reference)
#include <cuda_runtime.h>

// ComponentWiseSpline: rational-quadratic spline flow, forward + log|det J|.
// B=65536 rows, D=128 dims, K=8 interior bins.
// R15: R14 (8 elems/lane/iter, log-product, 9-slot identity table, 296x512)
//      + Horner-in-theta algebra (12 ops/elem body) + factored row product
//      P = (d0inv0*d1inv1)^2 * inner0*inner1.

#define BB 65536
#define DD 128
#define KK 8
#define NSLOT 9                          // identity | 8 interior
#define NQ (BB / 4)                      // 16384 row-quads
#define BLOCK 512
#define TEAMS 8                          // 2-warp teams per block
#define GRIDB 296                        // 148 SMs * 2 blocks
#define NSQ (GRIDB * TEAMS)              // 2368 quad-streams
#define MAXQ ((NQ + NSQ - 1) / NSQ)      // 7

// overlay: thresholds staging (1152 floats), then partials (1792 floats)
#define AUXN (TEAMS * 2 * MAXQ * 4 * 4)  // 1792 floats = 7 KB
#define PARTBASE(t, h, i) ((((t) * 2 + (h)) * MAXQ + (i)) * 16)

__device__ __forceinline__ float fsetge(float a, float b) {
    float r;
    asm("set.ge.f32.f32 %0, %1, %2;" : "=f"(r) : "f"(a), "f"(b));
    return r;
}

__global__ void __launch_bounds__(BLOCK, 2)
spline_kernel(const float* __restrict__ x,
              const float* __restrict__ uw,
              const float* __restrict__ uh,
              const float* __restrict__ ud,
              float* __restrict__ uout,
              float* __restrict__ ldout) {
    __shared__ float4 sTA[NSLOT * DD];   // 18 KB {invW, off, cumH, H}
    __shared__ float4 sTB[NSLOT * DD];   // 18 KB {delta, d0, g=delta-d0, e}
    __shared__ float  sAux[AUXN];        // 7 KB overlay

    const int tid  = threadIdx.x;
    const int lane = tid & 31;
    const int warp = tid >> 5;       // 0..15
    const int team = warp >> 1;      // 0..7
    const int half = warp & 1;       // which 64-dim half of the row

    // ---- per-block table build: thread dd (<128) builds dim dd ----
    if (tid < DD) {
        const float BOUND = 3.0f;
        const float MINW = 1e-3f, MINH = 1e-3f, MIND = 1e-3f, EPS = 1e-6f;
        const int dd = tid;

        float w[KK], h[KK];
        float m = -1e30f;
        #pragma unroll
        for (int k = 0; k < KK; k++) { w[k] = uw[dd * KK + k]; m = fmaxf(m, w[k]); }
        float s = 0.f;
        #pragma unroll
        for (int k = 0; k < KK; k++) { w[k] = expf(w[k] - m); s += w[k]; }
        float invs = 1.0f / s;
        #pragma unroll
        for (int k = 0; k < KK; k++) w[k] = MINW + (1.0f - MINW * KK) * (w[k] * invs);

        m = -1e30f;
        #pragma unroll
        for (int k = 0; k < KK; k++) { h[k] = uh[dd * KK + k]; m = fmaxf(m, h[k]); }
        s = 0.f;
        #pragma unroll
        for (int k = 0; k < KK; k++) { h[k] = expf(h[k] - m); s += h[k]; }
        invs = 1.0f / s;
        #pragma unroll
        for (int k = 0; k < KK; k++) h[k] = MINH + (1.0f - MINH * KK) * (h[k] * invs);

        float cw[KK + 1], ch[KK + 1];
        cw[0] = -BOUND; ch[0] = -BOUND;
        float accw = 0.f, acch = 0.f;
        #pragma unroll
        for (int k = 1; k < KK; k++) {
            accw += w[k - 1]; cw[k] = fmaf(2.0f * BOUND, accw, -BOUND);
            acch += h[k - 1]; ch[k] = fmaf(2.0f * BOUND, acch, -BOUND);
        }
        cw[KK] = BOUND; ch[KK] = BOUND;

        float dv[KK + 1];
        dv[0] = 1.0f - MIND; dv[KK] = 1.0f - MIND;
        #pragma unroll
        for (int k = 1; k < KK; k++) {
            float v = ud[dd * (KK - 1) + (k - 1)];
            dv[k] = MIND + fmaxf(v, 0.0f) + log1pf(expf(-fabsf(v)));
        }

        // slot remap: dim dd = hh*64 + 2*pos + c  ->  slot hh*64 + c*32 + pos
        const int hh  = dd >> 6;
        const int rem = dd & 63;
        const int s_slot = (hh << 6) + ((rem & 1) << 5) + (rem >> 1);

        // interior bins k -> slot k+1 (slots 1..8)
        #pragma unroll
        for (int k = 0; k < KK; k++) {
            float W = cw[k + 1] - cw[k];
            float H = ch[k + 1] - ch[k];
            float invW = 1.0f / W;
            float del  = H * invW;
            float d0 = dv[k], d1 = dv[k + 1];
            sTA[(k + 1) * DD + s_slot] = make_float4(invW, -cw[k] * invW, ch[k], H);
            sTB[(k + 1) * DD + s_slot] = make_float4(del, d0, del - d0,
                                                     d0 + d1 - 2.0f * del);
        }
        // identity slot 0 (both tails): u = x, derivative = 1
        sTA[0 * DD + s_slot] = make_float4(1.0f, 0.0f, 0.0f, 1.0f);
        sTB[0 * DD + s_slot] = make_float4(1.0f, 1.0f, 0.0f, 0.0f);

        // thresholds into overlay region
        sAux[0 * DD + s_slot] = -3.0f;
        #pragma unroll
        for (int t = 1; t < 8; t++) sAux[t * DD + s_slot] = cw[t] + EPS;
        sAux[8 * DD + s_slot] = __int_as_float(0x40400001);   // nextafter(3.0f)
    }
    __syncthreads();

    // ---- this lane's 2x9 thresholds into registers ----
    const int slotc0 = (half << 6) + lane;
    const int slotc1 = slotc0 + 32;
    float thr[2][9];
    #pragma unroll
    for (int j = 0; j < 9; j++) thr[0][j] = sAux[j * DD + slotc0];
    #pragma unroll
    for (int j = 0; j < 9; j++) thr[1][j] = sAux[j * DD + slotc1];
    __syncthreads();   // overlay handoff: thresholds read; partials may write

    const int S = blockIdx.x * TEAMS + team;     // quad-stream id, 0..NSQ-1
    const int cnt = (NQ - S + NSQ - 1) / NSQ;    // 6 or 7 quads
    const size_t STEP = (size_t)NSQ * 512;       // floats per stream step
    const int coloff = (half << 6) + (lane << 1);

    const float* px = x + (size_t)S * 512 + coloff;
    float*       pu = uout + (size_t)S * 512 + coloff;
    float2 xq[4], xn[4];
    #pragma unroll
    for (int r = 0; r < 4; r++)
        xq[r] = *reinterpret_cast<const float2*>(px + r * DD);

    for (int pi = 0; pi < cnt; pi++) {
        if (pi < cnt - 1) {
            #pragma unroll
            for (int r = 0; r < 4; r++)
                xn[r] = *reinterpret_cast<const float2*>(px + STEP + r * DD);
        }

        float P[4];
        #pragma unroll
        for (int r = 0; r < 4; r++) {
            float xin[2] = {xq[r].x, xq[r].y};
            float uo2[2], dinv[2], innr[2];
            #pragma unroll
            for (int c = 0; c < 2; c++) {
                const float xv = xin[c];
                // slot = 1 + interior bin; 0 for both tails (-8 on exit set)
                float s0 = fsetge(xv, thr[c][0]) + fsetge(xv, thr[c][1]);
                float s1 = fsetge(xv, thr[c][2]) + fsetge(xv, thr[c][3]);
                float s2 = fsetge(xv, thr[c][4]) + fsetge(xv, thr[c][5]);
                float s3 = fsetge(xv, thr[c][6]) + fsetge(xv, thr[c][7]);
                float kf = fmaf(fsetge(xv, thr[c][8]), -8.0f,
                                (s0 + s1) + (s2 + s3));
                const int idx = __float2int_rz(kf) * DD +
                                (c ? slotc1 : slotc0);

                const float4 A  = sTA[idx];   // invW, off, cumH, H
                const float4 Bv = sTB[idx];   // delta, d0, g=delta-d0, e

                const float th  = fmaf(xv, A.x, A.y);   // theta
                const float q   = fmaf(th, Bv.z, Bv.y); // δθ + d0(1-θ)
                const float Ht  = A.w * th;
                const float num = Ht * q;
                const float t   = Bv.w * th;            // eθ
                const float omt = 1.0f - th;
                const float den = fmaf(t, omt, Bv.x);   // δ + eθ(1-θ)
                const float inv = __fdividef(1.0f, den);
                uo2[c] = fmaf(num, inv, A.z);

                const float sI  = fmaf(Bv.z, 2.0f, t);  // 2g + eθ
                innr[c] = fmaf(th, sI, Bv.y);           // eθ²+2gθ+d0
                dinv[c] = Bv.x * inv;                   // δ/den
            }
            // deriv product over the 2 dims: (δ0inv0·δ1inv1)²·inner0·inner1
            const float dd2 = dinv[0] * dinv[1];
            P[r] = (dd2 * dd2) * (innr[0] * innr[1]);
            *reinterpret_cast<float2*>(pu + r * DD) =
                make_float2(uo2[0], uo2[1]);
        }

        // one log per row
        float la = __logf(P[0]);
        float lb = __logf(P[1]);
        float lc = __logf(P[2]);
        float ld = __logf(P[3]);

        // 3-step butterflies: lanes 0..3 hold 4-lane-group sums
        #pragma unroll
        for (int off = 16; off >= 4; off >>= 1) {
            la += __shfl_xor_sync(0xffffffffu, la, off);
            lb += __shfl_xor_sync(0xffffffffu, lb, off);
            lc += __shfl_xor_sync(0xffffffffu, lc, off);
            ld += __shfl_xor_sync(0xffffffffu, ld, off);
        }
        if (lane < 4) {
            float4* p = reinterpret_cast<float4*>(
                &sAux[PARTBASE(team, half, pi) + lane * 4]);
            *p = make_float4(la, lb, lc, ld);
        }

        px += STEP;
        pu += STEP;
        #pragma unroll
        for (int r = 0; r < 4; r++) xq[r] = xn[r];
    }
    __syncthreads();

    // ---- combine 8 partials per row (2 halves x 4 lane-groups) ----
    if (tid < TEAMS * MAXQ * 4) {
        const int tm  = tid / (MAXQ * 4);
        const int rem = tid - tm * (MAXQ * 4);
        const int qi  = rem >> 2;
        const int rb  = rem & 3;
        const int gq  = blockIdx.x * TEAMS + tm + qi * NSQ;
        if (gq < NQ) {
            float v = 0.f;
            #pragma unroll
            for (int hh = 0; hh < 2; hh++) {
                const int base = PARTBASE(tm, hh, qi);
                v += (sAux[base + 0 * 4 + rb] + sAux[base + 1 * 4 + rb]) +
                     (sAux[base + 2 * 4 + rb] + sAux[base + 3 * 4 + rb]);
            }
            ldout[4 * gq + rb] = v;
        }
    }
}

extern "C" void kernel_launch(void* const* d_in, const int* in_sizes, int n_in,
                              void* d_out, int out_size) {
    const float* x  = (const float*)d_in[0];
    const float* uw = (const float*)d_in[1];
    const float* uh = (const float*)d_in[2];
    const float* ud = (const float*)d_in[3];
    float* out = (float*)d_out;

    spline_kernel<<<GRIDB, BLOCK>>>(x, uw, uh, ud, out, out + (size_t)BB * DD);
}